// round 13
// baseline (speedup 1.0000x reference)
#include <cuda_runtime.h>

#define NB 16            // batch
#define NS 65            // segments per batch
#define NR 1040          // NB*NS rows
#define NW 256           // candidate positions per row
#define ND 128           // feature dim
#define T_PAD 2176       // padded time length of x
#define LSEQ 2048        // MAX_LEN_SEQ
#define MIN_SEG 32
#define NOUT (NB * LSEQ) // 32768 output rows
#define FULL 0xffffffffu
#define ROWS_PER_BLK 16  // 16 output rows (16KB) per block

__device__ int   g_rowstart[NR + 1];
__device__ uint2 g_desc[NR];      // .x = base row in x ((r/NS)*T_PAD+offset), .y = scale bits
__device__ int   g_L[1];

// Exact-boundary row count: smallest w in [0,NW] with floor(rn(w/sc)) >= Tm.
__device__ __forceinline__ int row_count(int Tm, float sc) {
    if (Tm <= 0) return 0;
    float wr = (float)Tm * sc;
    int wlo = (int)wr - 3;
    if (wlo < 0) wlo = 0;
    if (wlo >= NW) return NW;
    float fT = (float)Tm;
    int cnt = NW;
    #pragma unroll
    for (int j = 0; j < 8; j++) {
        int w = wlo + j;
        bool fail = (w < NW) && (floorf(__fdiv_rn((float)w, sc)) >= fT);
        if (fail && w < cnt) cnt = w;   // ascending -> min = first fail
    }
    return cnt;
}

// ---------------------------------------------------------------------------
// Setup (proven R11/R12 version). 1 block x 1024.
// ---------------------------------------------------------------------------
__global__ void __launch_bounds__(1024)
setup_kernel(const float* __restrict__ scales,
             const int* __restrict__ len_seq,
             const int* __restrict__ len_seg_raw) {
    __shared__ int sh_seg[NR];
    __shared__ int sh_off[NR];
    __shared__ int sh_ws[32];
    int tid  = threadIdx.x;
    int wid  = tid >> 5;
    int lane = tid & 31;

    for (int i = tid; i < NR; i += 1024) sh_seg[i] = len_seg_raw[i] + MIN_SEG;
    __syncthreads();

    if (wid < NB) {
        int base = wid * NS;
        int carry = 0;
        #pragma unroll
        for (int c = 0; c < 3; c++) {
            int i = c * 32 + lane;
            int v = (i < NS) ? sh_seg[base + i] : 0;
            int s = v;
            #pragma unroll
            for (int o = 1; o < 32; o <<= 1) {
                int u = __shfl_up_sync(FULL, s, o);
                if (lane >= o) s += u;
            }
            if (i < NS) sh_off[base + i] = carry + s - v;   // exclusive
            carry += __shfl_sync(FULL, s, 31);
        }
    }
    __syncthreads();

    float sc0 = 0.f, sc1 = 0.f;
    int a0 = 0, a1 = 0;
    int i0 = 2 * tid, i1 = 2 * tid + 1;
    if (i0 < NR) {
        int b = i0 / NS;
        sc0 = scales[i0] + 0.5f;
        a0 = row_count(min(sh_seg[i0] - 1, len_seq[b] - 1 - sh_off[i0]), sc0);
    }
    if (i1 < NR) {
        int b = i1 / NS;
        sc1 = scales[i1] + 0.5f;
        a1 = row_count(min(sh_seg[i1] - 1, len_seq[b] - 1 - sh_off[i1]), sc1);
    }

    int s = a0 + a1;
    int incl = s;
    #pragma unroll
    for (int o = 1; o < 32; o <<= 1) {
        int u = __shfl_up_sync(FULL, incl, o);
        if (lane >= o) incl += u;
    }
    if (lane == 31) sh_ws[wid] = incl;
    __syncthreads();
    if (wid == 0) {
        int ws = sh_ws[lane];
        #pragma unroll
        for (int o = 1; o < 32; o <<= 1) {
            int u = __shfl_up_sync(FULL, ws, o);
            if (lane >= o) ws += u;
        }
        sh_ws[lane] = ws;
    }
    __syncthreads();
    int warp_base = (wid > 0) ? sh_ws[wid - 1] : 0;
    incl += warp_base;
    int excl = incl - s;

    if (i0 < NR) {
        g_rowstart[i0] = excl;
        g_desc[i0] = make_uint2((unsigned)((i0 / NS) * T_PAD + sh_off[i0]),
                                __float_as_uint(sc0));
    }
    if (i1 < NR) {
        g_rowstart[i1] = excl + a0;
        g_desc[i1] = make_uint2((unsigned)((i1 / NS) * T_PAD + sh_off[i1]),
                                __float_as_uint(sc1));
    }
    if (tid == 519) {
        g_rowstart[NR] = incl;
        g_L[0] = incl / NB;
    }
}

// Warp-cooperative 2-round search: r = max{ r : rowstart[r] <= g }, plus rowstart[r].
__device__ __forceinline__ void warp_find(int g, int lane, int& r, int& rs) {
    int i1 = lane * 33;
    int v1 = g_rowstart[i1];
    unsigned m1 = __ballot_sync(FULL, v1 <= g);
    int h1 = 31 - __clz(m1);
    int b0 = h1 * 33;
    int i2 = b0 + 1 + lane;
    if (i2 > NR) i2 = NR;
    int v2 = g_rowstart[i2];
    unsigned m2 = __ballot_sync(FULL, v2 <= g);
    if (m2) {
        int h2 = 31 - __clz(m2);
        r  = b0 + 1 + h2;
        rs = __shfl_sync(FULL, v2, h2);
    } else {
        r  = b0;
        rs = __shfl_sync(FULL, v1, h1);
    }
}

__device__ __forceinline__ unsigned smem_u32(const void* p) {
    unsigned a;
    asm("{ .reg .u64 t; cvta.to.shared.u64 t, %1; cvt.u32.u64 %0, t; }"
        : "=r"(a) : "l"(p));
    return a;
}

// ---------------------------------------------------------------------------
// Gather: block = 16 consecutive output rows (one batch). Warp wib handles the
// pair (2wib, 2wib+1): one warp_find + reuse. Results staged in SMEM (STS),
// then ONE cp.async.bulk store of 16KB per block (stores leave the LSU path).
// ---------------------------------------------------------------------------
__global__ void __launch_bounds__(256)
gather_kernel(const float* __restrict__ x, float* __restrict__ out) {
#if __CUDA_ARCH__ >= 900
    cudaGridDependencySynchronize();   // PDL: wait for setup results
#endif
    __shared__ __align__(128) float4 sbuf[ROWS_PER_BLK * 32];   // 16KB
    int blk  = blockIdx.x;
    int lane = threadIdx.x & 31;
    int wib  = threadIdx.x >> 5;
    int L = g_L[0];

    int gid0 = blk * ROWS_PER_BLK + 2 * wib;   // pair of consecutive t, same batch
    int t0 = gid0 & (LSEQ - 1);
    int b  = gid0 >> 11;
    bool v0 = (t0 < L);
    bool v1 = (t0 + 1 < L);

    float lam0 = 0.f, lam1 = 0.f;
    float4 a0, c0, a1, c1;
    if (v0) {
        int g0 = b * L + t0;
        int r0, rs0;
        warp_find(g0, lane, r0, rs0);
        int nxt = g_rowstart[r0 + 1];
        uint2 d0 = g_desc[r0];
        {
            int w = g0 - rs0;
            float fs = __fdiv_rn((float)w, __uint_as_float(d0.y));
            float fl = floorf(fs);
            lam0 = fs - fl;
            const float4* p = (const float4*)(x + (size_t)((int)d0.x + (int)fl) * ND);
            a0 = p[lane]; c0 = p[lane + 32];
        }
        if (v1) {
            int g1 = g0 + 1;
            int r1, rs1; uint2 d1;
            if (nxt <= g1) {                   // rare segment-row crossing
                warp_find(g1, lane, r1, rs1);
                d1 = g_desc[r1];
            } else {
                r1 = r0; rs1 = rs0; d1 = d0;
            }
            int w = g1 - rs1;
            float fs = __fdiv_rn((float)w, __uint_as_float(d1.y));
            float fl = floorf(fs);
            lam1 = fs - fl;
            const float4* p = (const float4*)(x + (size_t)((int)d1.x + (int)fl) * ND);
            a1 = p[lane]; c1 = p[lane + 32];
        }
    }

    float4 y0 = make_float4(0.f, 0.f, 0.f, 0.f);
    float4 y1 = y0;
    if (v0) {
        float om = 1.0f - lam0;
        y0.x = om * a0.x + lam0 * c0.x;  y0.y = om * a0.y + lam0 * c0.y;
        y0.z = om * a0.z + lam0 * c0.z;  y0.w = om * a0.w + lam0 * c0.w;
    }
    if (v1) {
        float om = 1.0f - lam1;
        y1.x = om * a1.x + lam1 * c1.x;  y1.y = om * a1.y + lam1 * c1.y;
        y1.z = om * a1.z + lam1 * c1.z;  y1.w = om * a1.w + lam1 * c1.w;
    }
    sbuf[(2 * wib)     * 32 + lane] = y0;
    sbuf[(2 * wib + 1) * 32 + lane] = y1;
    __syncthreads();

    if (threadIdx.x == 0) {
        asm volatile("fence.proxy.async.shared::cta;" ::: "memory");
        unsigned src = smem_u32(sbuf);
        const float* dst = out + (size_t)blk * ROWS_PER_BLK * ND;
        asm volatile(
            "cp.async.bulk.global.shared::cta.bulk_group [%0], [%1], %2;"
            :: "l"(dst), "r"(src), "n"(ROWS_PER_BLK * ND * 4)
            : "memory");
        asm volatile("cp.async.bulk.commit_group;" ::: "memory");
        asm volatile("cp.async.bulk.wait_group 0;" ::: "memory");
    }
}

static inline void launch_pdl(void* fn, dim3 grid, dim3 block, void** args) {
    cudaLaunchConfig_t cfg = {};
    cfg.gridDim = grid;
    cfg.blockDim = block;
    cfg.dynamicSmemBytes = 0;
    cfg.stream = 0;
    cudaLaunchAttribute attr[1];
    attr[0].id = cudaLaunchAttributeProgrammaticStreamSerialization;
    attr[0].val.programmaticStreamSerializationAllowed = 1;
    cfg.attrs = attr;
    cfg.numAttrs = 1;
    cudaLaunchKernelExC(&cfg, fn, args);
}

extern "C" void kernel_launch(void* const* d_in, const int* in_sizes, int n_in,
                              void* d_out, int out_size) {
    const float* x           = (const float*)d_in[0];
    const float* scales      = (const float*)d_in[1];
    const int*   len_seq     = (const int*)d_in[2];
    const int*   len_seg_raw = (const int*)d_in[3];
    float* out = (float*)d_out;

    setup_kernel<<<1, 1024>>>(scales, len_seq, len_seg_raw);

    void* args[] = { (void*)&x, (void*)&out };
    launch_pdl((void*)gather_kernel, dim3(NOUT / ROWS_PER_BLK), dim3(256), args);
}